// round 1
// baseline (speedup 1.0000x reference)
#include <cuda_runtime.h>
#include <cuda_bf16.h>
#include <cstdint>

#define N_NODES 100000
#define N_EDGES 1600000
#define E_TOT   (N_EDGES + N_NODES)   // self loops appended
#define N_GRAPHS 1024
#define EPS_BN 1e-5f

// ----------------------------- scratch (device globals) -----------------------------
__device__ int   g_is64;
__device__ int   g_src[E_TOT];
__device__ int   g_dst[E_TOT];
__device__ int   g_batch[N_NODES];
__device__ int   g_deg[N_NODES];
__device__ int   g_off[N_NODES + 1];
__device__ int   g_cur[N_NODES];
__device__ int   g_csr[E_TOT];
__device__ float g_hlin[N_NODES * 128];   // post-GEMM features (attn input)
__device__ float g_feat[N_NODES * 128];   // node features (attn output / GEMM input)
__device__ float g_als[N_NODES * 4];
__device__ float g_ald[N_NODES * 4];
__device__ float g_bnsum[256];            // [0:128) sum, [128:256) sumsq
__device__ float g_pool[N_GRAPHS * 128];  // mean (0..63) || max (64..127)

// ----------------------------- utility -----------------------------
__device__ __forceinline__ float eluf(float v) { return v > 0.f ? v : expm1f(v); }

// ----------------------------- dtype detection -----------------------------
__global__ void detect_kernel(const void* ei) {
    __shared__ int any;
    if (threadIdx.x == 0) any = 0;
    __syncthreads();
    const int* p = (const int*)ei;
    int local = 0;
    for (int i = threadIdx.x; i < 2048; i += 256)
        if (p[2 * i + 1] != 0) local = 1;
    if (local) atomicOr(&any, 1);
    __syncthreads();
    if (threadIdx.x == 0) g_is64 = any ? 0 : 1;
}

// convert edges/batch to int32 scratch; append self loops; zero degree
__global__ void convert_kernel(const void* ei, const void* batch) {
    int i = blockIdx.x * 256 + threadIdx.x;
    int is64 = g_is64;
    if (i < E_TOT) {
        int s, d;
        if (i < N_EDGES) {
            if (is64) {
                s = (int)((const long long*)ei)[i];
                d = (int)((const long long*)ei)[N_EDGES + i];
            } else {
                s = ((const int*)ei)[i];
                d = ((const int*)ei)[N_EDGES + i];
            }
        } else {
            s = d = i - N_EDGES;
        }
        g_src[i] = s;
        g_dst[i] = d;
    }
    if (i < N_NODES) {
        g_batch[i] = is64 ? (int)((const long long*)batch)[i] : ((const int*)batch)[i];
        g_deg[i] = 0;
    }
}

__global__ void count_kernel() {
    int i = blockIdx.x * 256 + threadIdx.x;
    if (i < E_TOT) atomicAdd(&g_deg[g_dst[i]], 1);
}

// single-block exclusive scan over 100001 entries
__global__ void scan_kernel() {
    __shared__ int ssum[1024];
    const int CH = (N_NODES + 1023) / 1024;  // 98
    int t = threadIdx.x;
    int begin = t * CH;
    int local = 0;
    for (int i = 0; i < CH; i++) {
        int idx = begin + i;
        if (idx < N_NODES) local += g_deg[idx];
    }
    ssum[t] = local;
    __syncthreads();
    for (int off = 1; off < 1024; off <<= 1) {
        int v = (t >= off) ? ssum[t - off] : 0;
        __syncthreads();
        ssum[t] += v;
        __syncthreads();
    }
    int run = (t == 0) ? 0 : ssum[t - 1];
    for (int i = 0; i < CH; i++) {
        int idx = begin + i;
        if (idx < N_NODES) {
            g_off[idx] = run;
            g_cur[idx] = run;
            run += g_deg[idx];
        }
    }
    if (t == 1023) g_off[N_NODES] = ssum[1023];
}

__global__ void fill_kernel() {
    int i = blockIdx.x * 256 + threadIdx.x;
    if (i < E_TOT) {
        int p = atomicAdd(&g_cur[g_dst[i]], 1);
        g_csr[p] = g_src[i];
    }
}

// ----------------------------- layer-1 GEMM (5 -> 128, no bias) -----------------------------
__global__ void gemm1_kernel(const float* __restrict__ x, const float* __restrict__ W1) {
    int t = blockIdx.x * 256 + threadIdx.x;
    if (t >= N_NODES * 128) return;
    int n = t >> 7, j = t & 127;
    const float* xr = x + n * 5;
    float acc = 0.f;
#pragma unroll
    for (int k = 0; k < 5; k++) acc += __ldg(&xr[k]) * __ldg(&W1[k * 128 + j]);
    g_hlin[t] = acc;
}

// ----------------------------- 128 -> OUTC GEMM (g_feat @ W -> g_hlin, no bias) ------------
template <int OUTC>
__global__ void gemm_kernel(const float* __restrict__ W) {
    __shared__ float As[64][33];
    __shared__ float Ws[32][OUTC];
    int t = threadIdx.x;   // 256
    int tc = t & 31;
    int tn = t >> 5;       // 0..7
    int nodeBase = blockIdx.x * 64;
    constexpr int CJ = OUTC / 32;
    float acc[8][CJ];
#pragma unroll
    for (int r = 0; r < 8; r++)
#pragma unroll
        for (int cj = 0; cj < CJ; cj++) acc[r][cj] = 0.f;

    for (int kc = 0; kc < 4; kc++) {
#pragma unroll
        for (int j = 0; j < 8; j++) {
            int idx = t + j * 256;
            int row = idx >> 5, col = idx & 31;
            int node = nodeBase + row;
            As[row][col] = (node < N_NODES) ? g_feat[node * 128 + kc * 32 + col] : 0.f;
        }
#pragma unroll
        for (int j = 0; j < (32 * OUTC) / 256; j++) {
            int idx = t + j * 256;
            int r = idx / OUTC, c2 = idx % OUTC;
            Ws[r][c2] = W[(kc * 32 + r) * OUTC + c2];
        }
        __syncthreads();
#pragma unroll
        for (int kk = 0; kk < 32; kk++) {
            float w[CJ];
#pragma unroll
            for (int cj = 0; cj < CJ; cj++) w[cj] = Ws[kk][tc + 32 * cj];
#pragma unroll
            for (int r = 0; r < 8; r++) {
                float a = As[tn * 8 + r][kk];
#pragma unroll
                for (int cj = 0; cj < CJ; cj++) acc[r][cj] += a * w[cj];
            }
        }
        __syncthreads();
    }
#pragma unroll
    for (int r = 0; r < 8; r++) {
        int node = nodeBase + tn * 8 + r;
        if (node < N_NODES) {
#pragma unroll
            for (int cj = 0; cj < CJ; cj++)
                g_hlin[node * OUTC + tc + 32 * cj] = acc[r][cj];
        }
    }
}

// ----------------------------- attention logits per node (H=4,C=32) -----------------------------
__global__ void als_kernel(const float* __restrict__ a_src, const float* __restrict__ a_dst) {
    int t = blockIdx.x * 256 + threadIdx.x;
    if (t >= N_NODES * 4) return;
    int n = t >> 2, h = t & 3;
    const float4* hp = (const float4*)(g_hlin + n * 128 + h * 32);
    const float4* asp = (const float4*)(a_src + h * 32);
    const float4* adp = (const float4*)(a_dst + h * 32);
    float s1 = 0.f, s2 = 0.f;
#pragma unroll
    for (int j = 0; j < 8; j++) {
        float4 hv = hp[j], av = __ldg(&asp[j]), dv = __ldg(&adp[j]);
        s1 += hv.x * av.x + hv.y * av.y + hv.z * av.z + hv.w * av.w;
        s2 += hv.x * dv.x + hv.y * dv.y + hv.z * dv.z + hv.w * dv.w;
    }
    g_als[t] = s1;
    g_ald[t] = s2;
}

// H=1,C=64 version (layer 3)
__global__ void als3_kernel(const float* __restrict__ a_src, const float* __restrict__ a_dst) {
    int n = blockIdx.x * 256 + threadIdx.x;
    if (n >= N_NODES) return;
    const float4* hp = (const float4*)(g_hlin + n * 64);
    const float4* asp = (const float4*)a_src;
    const float4* adp = (const float4*)a_dst;
    float s1 = 0.f, s2 = 0.f;
#pragma unroll
    for (int j = 0; j < 16; j++) {
        float4 hv = hp[j], av = __ldg(&asp[j]), dv = __ldg(&adp[j]);
        s1 += hv.x * av.x + hv.y * av.y + hv.z * av.z + hv.w * av.w;
        s2 += hv.x * dv.x + hv.y * dv.y + hv.z * dv.z + hv.w * dv.w;
    }
    g_als[n] = s1;
    g_ald[n] = s2;
}

// ----------------------------- GAT aggregation: warp per dst, online softmax ----------------
// HC = H*C total channels; K = HC/32 channels per lane; head of k = (k*32)/C
template <int H, int HC, bool ELU_OUT>
__global__ void attn_kernel(const float* __restrict__ bias) {
    constexpr int K = HC / 32;
    constexpr int C = HC / H;
    int node = (blockIdx.x * blockDim.x + threadIdx.x) >> 5;
    int lane = threadIdx.x & 31;
    if (node >= N_NODES) return;

    float ad[H], m[H], s[H], acc[K];
#pragma unroll
    for (int h = 0; h < H; h++) {
        ad[h] = g_ald[node * H + h];
        m[h] = __int_as_float(0xff800000);  // -inf
        s[h] = 0.f;
    }
#pragma unroll
    for (int k = 0; k < K; k++) acc[k] = 0.f;

    int beg = g_off[node], end = g_off[node + 1];
    for (int i = beg; i < end; i++) {
        int src = __ldg(&g_csr[i]);
        float e[H], p[H];
#pragma unroll
        for (int h = 0; h < H; h++) {
            float v = __ldg(&g_als[src * H + h]) + ad[h];
            e[h] = v > 0.f ? v : 0.2f * v;
        }
        float hv[K];
#pragma unroll
        for (int k = 0; k < K; k++) hv[k] = g_hlin[src * HC + k * 32 + lane];
#pragma unroll
        for (int h = 0; h < H; h++) {
            if (e[h] <= m[h]) {
                p[h] = __expf(e[h] - m[h]);
                s[h] += p[h];
            } else {
                float sc = __expf(m[h] - e[h]);
                s[h] = s[h] * sc + 1.f;
#pragma unroll
                for (int k = 0; k < K; k++)
                    if ((k * 32) / C == h) acc[k] *= sc;
                m[h] = e[h];
                p[h] = 1.f;
            }
        }
#pragma unroll
        for (int k = 0; k < K; k++) acc[k] += p[(k * 32) / C] * hv[k];
    }

#pragma unroll
    for (int k = 0; k < K; k++) {
        int h = (k * 32) / C;
        float v = acc[k] / (s[h] + 1e-16f) + __ldg(&bias[k * 32 + lane]);
        if (ELU_OUT) v = eluf(v);
        g_feat[node * HC + k * 32 + lane] = v;
    }
}

// ----------------------------- batch norm -----------------------------
__global__ void zero_bnsum_kernel() {
    if (threadIdx.x < 256) g_bnsum[threadIdx.x] = 0.f;
}

__global__ void bnstats_kernel() {
    int c = threadIdx.x;  // 128
    int n0 = blockIdx.x * 128;
    float s = 0.f, sq = 0.f;
    for (int r = 0; r < 128; r++) {
        int n = n0 + r;
        if (n < N_NODES) {
            float v = g_feat[n * 128 + c];
            s += v;
            sq += v * v;
        }
    }
    atomicAdd(&g_bnsum[c], s);
    atomicAdd(&g_bnsum[128 + c], sq);
}

__global__ void bnnorm_kernel(const float* __restrict__ g, const float* __restrict__ be) {
    int t = blockIdx.x * 256 + threadIdx.x;
    if (t >= N_NODES * 128) return;
    int c = t & 127;
    const float invN = 1.f / (float)N_NODES;
    float mu = g_bnsum[c] * invN;
    float var = g_bnsum[128 + c] * invN - mu * mu;
    float rs = rsqrtf(var + EPS_BN);
    float v = (g_feat[t] - mu) * rs * __ldg(&g[c]) + __ldg(&be[c]);
    g_feat[t] = eluf(v);
}

// ----------------------------- pooling: one block per graph (batch is sorted) ----------------
__device__ __forceinline__ int lower_bound_batch(int key) {
    int lo = 0, hi = N_NODES;
    while (lo < hi) {
        int mid = (lo + hi) >> 1;
        if (g_batch[mid] < key) lo = mid + 1;
        else hi = mid;
    }
    return lo;
}

__global__ void pool_kernel() {
    int gidx = blockIdx.x;
    __shared__ int se[2];
    if (threadIdx.x == 0) se[0] = lower_bound_batch(gidx);
    if (threadIdx.x == 1) se[1] = lower_bound_batch(gidx + 1);
    __syncthreads();
    int beg = se[0], end = se[1];
    int c = threadIdx.x & 63, sl = threadIdx.x >> 6;  // 128 threads: 2 slices x 64 ch
    float sum = 0.f, mx = __int_as_float(0xff800000);
    for (int n = beg + sl; n < end; n += 2) {
        float v = g_feat[n * 64 + c];
        sum += v;
        mx = fmaxf(mx, v);
    }
    __shared__ float shs[128], shm[128];
    shs[threadIdx.x] = sum;
    shm[threadIdx.x] = mx;
    __syncthreads();
    if (sl == 0) {
        sum += shs[64 + c];
        mx = fmaxf(mx, shm[64 + c]);
        int cnt = end - beg;
        float mean = (cnt > 0) ? sum / (float)cnt : 0.f;
        float maxv = (cnt > 0) ? mx : 0.f;
        g_pool[gidx * 128 + c] = mean;
        g_pool[gidx * 128 + 64 + c] = maxv;
    }
}

// ----------------------------- classifier -----------------------------
__global__ void final_kernel(const float* __restrict__ fc1w, const float* __restrict__ fc1b,
                             const float* __restrict__ fc2w, const float* __restrict__ fc2b,
                             float* __restrict__ out) {
    int gidx = blockIdx.x;
    int c = threadIdx.x;  // 64
    __shared__ float hg[128];
    hg[c] = g_pool[gidx * 128 + c];
    hg[c + 64] = g_pool[gidx * 128 + 64 + c];
    __syncthreads();
    float acc = __ldg(&fc1b[c]);
#pragma unroll 8
    for (int k = 0; k < 128; k++) acc += hg[k] * __ldg(&fc1w[k * 64 + c]);
    float z = eluf(acc);
    float part = z * __ldg(&fc2w[c]);
#pragma unroll
    for (int off = 16; off; off >>= 1) part += __shfl_xor_sync(0xffffffffu, part, off);
    __shared__ float warpsum[2];
    if ((c & 31) == 0) warpsum[c >> 5] = part;
    __syncthreads();
    if (c == 0) out[gidx] = warpsum[0] + warpsum[1] + __ldg(&fc2b[0]);
}

// ----------------------------- launch -----------------------------
extern "C" void kernel_launch(void* const* d_in, const int* in_sizes, int n_in,
                              void* d_out, int out_size) {
    const float* x      = (const float*)d_in[0];
    const void*  ei     = d_in[1];
    const void*  batch  = d_in[2];
    const float* W1     = (const float*)d_in[3];
    const float* a1_src = (const float*)d_in[4];
    const float* a1_dst = (const float*)d_in[5];
    const float* b1     = (const float*)d_in[6];
    const float* g1     = (const float*)d_in[7];
    const float* be1    = (const float*)d_in[8];
    const float* W2     = (const float*)d_in[9];
    const float* a2_src = (const float*)d_in[10];
    const float* a2_dst = (const float*)d_in[11];
    const float* b2     = (const float*)d_in[12];
    const float* g2     = (const float*)d_in[13];
    const float* be2    = (const float*)d_in[14];
    const float* W3     = (const float*)d_in[15];
    const float* a3_src = (const float*)d_in[16];
    const float* a3_dst = (const float*)d_in[17];
    const float* b3     = (const float*)d_in[18];
    const float* fc1_w  = (const float*)d_in[19];
    const float* fc1_b  = (const float*)d_in[20];
    const float* fc2_w  = (const float*)d_in[21];
    const float* fc2_b  = (const float*)d_in[22];
    float* out = (float*)d_out;

    const int EB = (E_TOT + 255) / 256;             // edge-grid blocks
    const int NB128 = (N_NODES * 128 + 255) / 256;  // elementwise over N*128
    const int ATTN_B = (N_NODES + 7) / 8;           // 8 warps / block

    // graph structure (CSR by dst), rebuilt every call (deterministic inputs)
    detect_kernel<<<1, 256>>>(ei);
    convert_kernel<<<EB, 256>>>(ei, batch);
    count_kernel<<<EB, 256>>>();
    scan_kernel<<<1, 1024>>>();
    fill_kernel<<<EB, 256>>>();

    // ---- layer 1: 5 -> 4x32, concat; BN + ELU ----
    gemm1_kernel<<<NB128, 256>>>(x, W1);
    als_kernel<<<(N_NODES * 4 + 255) / 256, 256>>>(a1_src, a1_dst);
    attn_kernel<4, 128, false><<<ATTN_B, 256>>>(b1);
    zero_bnsum_kernel<<<1, 256>>>();
    bnstats_kernel<<<(N_NODES + 127) / 128, 128>>>();
    bnnorm_kernel<<<NB128, 256>>>(g1, be1);

    // ---- layer 2: 128 -> 4x32, concat; BN + ELU ----
    gemm_kernel<128><<<(N_NODES + 63) / 64, 256>>>(W2);
    als_kernel<<<(N_NODES * 4 + 255) / 256, 256>>>(a2_src, a2_dst);
    attn_kernel<4, 128, false><<<ATTN_B, 256>>>(b2);
    zero_bnsum_kernel<<<1, 256>>>();
    bnstats_kernel<<<(N_NODES + 127) / 128, 128>>>();
    bnnorm_kernel<<<NB128, 256>>>(g2, be2);

    // ---- layer 3: 128 -> 64, single head; ELU fused into attn epilogue ----
    gemm_kernel<64><<<(N_NODES + 63) / 64, 256>>>(W3);
    als3_kernel<<<(N_NODES + 255) / 256, 256>>>(a3_src, a3_dst);
    attn_kernel<1, 64, true><<<ATTN_B, 256>>>(b3);

    // ---- readout ----
    pool_kernel<<<N_GRAPHS, 128>>>();
    final_kernel<<<N_GRAPHS, 64>>>(fc1_w, fc1_b, fc2_w, fc2_b, out);
}

// round 2
// speedup vs baseline: 1.6121x; 1.6121x over previous
#include <cuda_runtime.h>
#include <cuda_bf16.h>
#include <cstdint>

#define N_NODES 100000
#define N_EDGES 1600000
#define E_TOT   (N_EDGES + N_NODES)   // self loops appended
#define N_GRAPHS 1024
#define EPS_BN 1e-5f
#define SCAN_B 98                      // ceil(N_NODES / 1024)

// ----------------------------- scratch (device globals) -----------------------------
__device__ int   g_is64;
__device__ int   g_src[E_TOT];
__device__ int   g_dst[E_TOT];
__device__ int   g_batch[N_NODES];
__device__ int   g_deg[N_NODES];
__device__ int   g_off[N_NODES + 1];
__device__ int   g_cur[N_NODES];
__device__ int   g_csr[E_TOT];
__device__ int   g_bsum[SCAN_B];
__device__ float g_hlin[N_NODES * 128];   // post-GEMM features (attn input)
__device__ float g_feat[N_NODES * 128];   // node features (attn output / GEMM input)
__device__ float g_als[N_NODES * 4];
__device__ float g_ald[N_NODES * 4];
__device__ float g_bnsum[256];            // [0:128) sum, [128:256) sumsq
__device__ float g_pool[N_GRAPHS * 128];  // mean (0..63) || max (64..127)

// ----------------------------- utility -----------------------------
__device__ __forceinline__ float eluf(float v) { return v > 0.f ? v : expm1f(v); }

__device__ __forceinline__ unsigned long long pack2(float x, float y) {
    unsigned long long r;
    asm("mov.b64 %0, {%1, %2};" : "=l"(r) : "f"(x), "f"(y));
    return r;
}
__device__ __forceinline__ float2 unpack2(unsigned long long v) {
    float2 r;
    asm("mov.b64 {%0, %1}, %2;" : "=f"(r.x), "=f"(r.y) : "l"(v));
    return r;
}
#define FMA_F32X2(acc, a, b) \
    asm("fma.rn.f32x2 %0, %1, %2, %0;" : "+l"(acc) : "l"(a), "l"(b))

// ----------------------------- dtype detection -----------------------------
__global__ void detect_kernel(const void* ei) {
    __shared__ int any;
    if (threadIdx.x == 0) any = 0;
    __syncthreads();
    const int* p = (const int*)ei;
    int local = 0;
    for (int i = threadIdx.x; i < 2048; i += 256)
        if (p[2 * i + 1] != 0) local = 1;
    if (local) atomicOr(&any, 1);
    __syncthreads();
    if (threadIdx.x == 0) g_is64 = any ? 0 : 1;
}

__global__ void zero_deg_kernel() {
    int i = blockIdx.x * 256 + threadIdx.x;
    if (i < N_NODES) g_deg[i] = 0;
}

// convert edges/batch to int32 scratch; append self loops; count degree (fused)
__global__ void convert_kernel(const void* ei, const void* batch) {
    int i = blockIdx.x * 256 + threadIdx.x;
    int is64 = g_is64;
    if (i < E_TOT) {
        int s, d;
        if (i < N_EDGES) {
            if (is64) {
                s = (int)((const long long*)ei)[i];
                d = (int)((const long long*)ei)[N_EDGES + i];
            } else {
                s = ((const int*)ei)[i];
                d = ((const int*)ei)[N_EDGES + i];
            }
        } else {
            s = d = i - N_EDGES;
        }
        g_src[i] = s;
        g_dst[i] = d;
        atomicAdd(&g_deg[d], 1);
    }
    if (i < N_NODES) {
        g_batch[i] = is64 ? (int)((const long long*)batch)[i] : ((const int*)batch)[i];
    }
}

// ----------------------------- hierarchical exclusive scan -----------------------------
__global__ void scan_partial_kernel() {   // grid=SCAN_B, 512 thr; block sums 1024 degs
    __shared__ int sh[512];
    int t = threadIdx.x;
    int base = blockIdx.x * 1024;
    int i0 = base + t, i1 = base + 512 + t;
    int v = ((i0 < N_NODES) ? g_deg[i0] : 0) + ((i1 < N_NODES) ? g_deg[i1] : 0);
    sh[t] = v;
    __syncthreads();
    for (int o = 256; o; o >>= 1) {
        if (t < o) sh[t] += sh[t + o];
        __syncthreads();
    }
    if (t == 0) g_bsum[blockIdx.x] = sh[0];
}

__global__ void scan_mid_kernel() {   // 1 block 128 thr: exclusive scan of SCAN_B partials
    __shared__ int sh[128];
    int t = threadIdx.x;
    int orig = (t < SCAN_B) ? g_bsum[t] : 0;
    sh[t] = orig;
    __syncthreads();
    for (int o = 1; o < 128; o <<= 1) {
        int v = (t >= o) ? sh[t - o] : 0;
        __syncthreads();
        sh[t] += v;
        __syncthreads();
    }
    if (t < SCAN_B) g_bsum[t] = sh[t] - orig;   // exclusive base
    if (t == 0) g_off[N_NODES] = E_TOT;
}

__global__ void scan_final_kernel() {  // grid=SCAN_B, 512 thr; 2 elems/thread
    __shared__ int wsum[16];
    int t = threadIdx.x;
    int base = blockIdx.x * 1024;
    int i0 = base + 2 * t, i1 = i0 + 1;
    int d0 = (i0 < N_NODES) ? g_deg[i0] : 0;
    int d1 = (i1 < N_NODES) ? g_deg[i1] : 0;
    int tsum = d0 + d1;
    int lane = t & 31, wid = t >> 5;
    int v = tsum;
#pragma unroll
    for (int o = 1; o < 32; o <<= 1) {
        int u = __shfl_up_sync(0xffffffffu, v, o);
        if (lane >= o) v += u;
    }
    if (lane == 31) wsum[wid] = v;
    __syncthreads();
    if (t < 16) {
        int w = wsum[t];
#pragma unroll
        for (int o = 1; o < 16; o <<= 1) {
            int u = __shfl_up_sync(0xffffu, w, o);
            if (t >= o) w += u;
        }
        wsum[t] = w;
    }
    __syncthreads();
    int excl = v - tsum + (wid ? wsum[wid - 1] : 0) + g_bsum[blockIdx.x];
    if (i0 < N_NODES) { g_off[i0] = excl;      g_cur[i0] = excl; }
    if (i1 < N_NODES) { g_off[i1] = excl + d0; g_cur[i1] = excl + d0; }
}

__global__ void fill_kernel() {
    int i = blockIdx.x * 256 + threadIdx.x;
    if (i < E_TOT) {
        int p = atomicAdd(&g_cur[g_dst[i]], 1);
        g_csr[p] = g_src[i];
    }
}

// ----------------------------- layer-1 GEMM (5 -> 128, vectorized) -----------------------------
__global__ void gemm1_kernel(const float* __restrict__ x, const float* __restrict__ W1) {
    int t = blockIdx.x * 256 + threadIdx.x;   // over N_NODES*64 channel-pairs
    if (t >= N_NODES * 64) return;
    int n = t >> 6, j = t & 63;
    const float* xr = x + n * 5;
    const float2* Wp = (const float2*)W1;
    float2 acc = make_float2(0.f, 0.f);
#pragma unroll
    for (int k = 0; k < 5; k++) {
        float xv = __ldg(&xr[k]);
        float2 w = __ldg(&Wp[k * 64 + j]);
        acc.x += xv * w.x;
        acc.y += xv * w.y;
    }
    ((float2*)g_hlin)[t] = acc;
}

// ----------------------------- 128 -> OUTC GEMM via FFMA2 ------------------------------------
template <int OUTC>
__global__ void gemm_kernel(const float* __restrict__ W) {
    constexpr int CJ2 = OUTC / 64;             // channel-pairs per thread
    __shared__ float As[64][33];
    __shared__ unsigned long long Ws2[32][OUTC / 2];
    int t = threadIdx.x;   // 256
    int tc = t & 31;       // channel-pair lane
    int tn = t >> 5;       // row group 0..7
    int nodeBase = blockIdx.x * 64;

    unsigned long long acc[8][CJ2];
#pragma unroll
    for (int r = 0; r < 8; r++)
#pragma unroll
        for (int cj = 0; cj < CJ2; cj++) acc[r][cj] = 0ull;

    const float2* Wp = (const float2*)W;
    for (int kc = 0; kc < 4; kc++) {
#pragma unroll
        for (int j = 0; j < 8; j++) {
            int idx = t + j * 256;
            int row = idx >> 5, col = idx & 31;
            int node = nodeBase + row;
            As[row][col] = (node < N_NODES) ? g_feat[node * 128 + kc * 32 + col] : 0.f;
        }
#pragma unroll
        for (int j = 0; j < (32 * OUTC / 2) / 256; j++) {
            int idx = t + j * 256;
            int r = idx / (OUTC / 2), c2 = idx % (OUTC / 2);
            float2 w = __ldg(&Wp[(kc * 32 + r) * (OUTC / 2) + c2]);
            Ws2[r][c2] = pack2(w.x, w.y);
        }
        __syncthreads();
#pragma unroll
        for (int kk = 0; kk < 32; kk++) {
            unsigned long long w[CJ2];
#pragma unroll
            for (int cj = 0; cj < CJ2; cj++) w[cj] = Ws2[kk][tc + 32 * cj];
#pragma unroll
            for (int r = 0; r < 8; r++) {
                float a = As[tn * 8 + r][kk];
                unsigned long long a2 = pack2(a, a);
#pragma unroll
                for (int cj = 0; cj < CJ2; cj++) FMA_F32X2(acc[r][cj], a2, w[cj]);
            }
        }
        __syncthreads();
    }
#pragma unroll
    for (int r = 0; r < 8; r++) {
        int node = nodeBase + tn * 8 + r;
        if (node < N_NODES) {
            float2* outp = (float2*)(g_hlin + node * OUTC);
#pragma unroll
            for (int cj = 0; cj < CJ2; cj++) outp[tc + 32 * cj] = unpack2(acc[r][cj]);
        }
    }
}

// ----------------------------- attention logits per node -----------------------------
__global__ void als_kernel(const float* __restrict__ a_src, const float* __restrict__ a_dst) {
    int t = blockIdx.x * 256 + threadIdx.x;
    if (t >= N_NODES * 4) return;
    int n = t >> 2, h = t & 3;
    const float4* hp = (const float4*)(g_hlin + n * 128 + h * 32);
    const float4* asp = (const float4*)(a_src + h * 32);
    const float4* adp = (const float4*)(a_dst + h * 32);
    float s1 = 0.f, s2 = 0.f;
#pragma unroll
    for (int j = 0; j < 8; j++) {
        float4 hv = hp[j], av = __ldg(&asp[j]), dv = __ldg(&adp[j]);
        s1 += hv.x * av.x + hv.y * av.y + hv.z * av.z + hv.w * av.w;
        s2 += hv.x * dv.x + hv.y * dv.y + hv.z * dv.z + hv.w * dv.w;
    }
    g_als[t] = s1;
    g_ald[t] = s2;
}

__global__ void als3_kernel(const float* __restrict__ a_src, const float* __restrict__ a_dst) {
    int n = blockIdx.x * 256 + threadIdx.x;
    if (n >= N_NODES) return;
    const float4* hp = (const float4*)(g_hlin + n * 64);
    const float4* asp = (const float4*)a_src;
    const float4* adp = (const float4*)a_dst;
    float s1 = 0.f, s2 = 0.f;
#pragma unroll
    for (int j = 0; j < 16; j++) {
        float4 hv = hp[j], av = __ldg(&asp[j]), dv = __ldg(&adp[j]);
        s1 += hv.x * av.x + hv.y * av.y + hv.z * av.z + hv.w * av.w;
        s2 += hv.x * dv.x + hv.y * dv.y + hv.z * dv.z + hv.w * dv.w;
    }
    g_als[n] = s1;
    g_ald[n] = s2;
}

// ----------------------------- GAT aggregation: warp/dst, channel-contiguous lanes -----------
// lane owns channels [lane*K, lane*K+K); head is uniform per lane (K divides C).
template <int H, int HC, bool ELU_OUT>
__global__ void attn_kernel(const float* __restrict__ bias) {
    constexpr int K = HC / 32;
    constexpr int C = HC / H;
    int node = (blockIdx.x * blockDim.x + threadIdx.x) >> 5;
    int lane = threadIdx.x & 31;
    if (node >= N_NODES) return;
    const int h0 = (lane * K) / C;

    float ad = g_ald[node * H + h0];
    float m = __int_as_float(0xff800000);
    float s = 0.f;
    float acc[K];
#pragma unroll
    for (int k = 0; k < K; k++) acc[k] = 0.f;

    int beg = g_off[node], end = g_off[node + 1];
#pragma unroll 2
    for (int i = beg; i < end; i++) {
        int src = __ldg(&g_csr[i]);
        float v = __ldg(&g_als[src * H + h0]) + ad;
        float e = v > 0.f ? v : 0.2f * v;
        float hv[K];
        if (K == 4) {
            float4 q = *(const float4*)(g_hlin + src * HC + lane * 4);
            hv[0] = q.x; hv[1] = q.y; hv[2] = q.z; hv[3] = q.w;
        } else {
            float2 q = *(const float2*)(g_hlin + src * HC + lane * 2);
            hv[0] = q.x; hv[1] = q.y;
        }
        float newm = fmaxf(m, e);
        float sc = __expf(m - newm);   // first iter: exp(-inf) = 0
        float p  = __expf(e - newm);
        s = s * sc + p;
#pragma unroll
        for (int k = 0; k < K; k++) acc[k] = acc[k] * sc + p * hv[k];
        m = newm;
    }

    float inv = 1.f / (s + 1e-16f);
    if (K == 4) {
        float4 o;
        o.x = acc[0] * inv + __ldg(&bias[lane * 4 + 0]);
        o.y = acc[1] * inv + __ldg(&bias[lane * 4 + 1]);
        o.z = acc[2] * inv + __ldg(&bias[lane * 4 + 2]);
        o.w = acc[3] * inv + __ldg(&bias[lane * 4 + 3]);
        if (ELU_OUT) { o.x = eluf(o.x); o.y = eluf(o.y); o.z = eluf(o.z); o.w = eluf(o.w); }
        *(float4*)(g_feat + node * HC + lane * 4) = o;
    } else {
        float2 o;
        o.x = acc[0] * inv + __ldg(&bias[lane * 2 + 0]);
        o.y = acc[1] * inv + __ldg(&bias[lane * 2 + 1]);
        if (ELU_OUT) { o.x = eluf(o.x); o.y = eluf(o.y); }
        *(float2*)(g_feat + node * HC + lane * 2) = o;
    }
}

// ----------------------------- batch norm -----------------------------
__global__ void zero_bnsum_kernel() {
    if (threadIdx.x < 256) g_bnsum[threadIdx.x] = 0.f;
}

__global__ void bnstats_kernel() {
    int c = threadIdx.x;  // 128
    int n0 = blockIdx.x * 128;
    float s = 0.f, sq = 0.f;
    for (int r = 0; r < 128; r++) {
        int n = n0 + r;
        if (n < N_NODES) {
            float v = g_feat[n * 128 + c];
            s += v;
            sq += v * v;
        }
    }
    atomicAdd(&g_bnsum[c], s);
    atomicAdd(&g_bnsum[128 + c], sq);
}

__global__ void bnnorm_kernel(const float* __restrict__ g, const float* __restrict__ be) {
    int t = blockIdx.x * 256 + threadIdx.x;
    if (t >= N_NODES * 128) return;
    int c = t & 127;
    const float invN = 1.f / (float)N_NODES;
    float mu = g_bnsum[c] * invN;
    float var = g_bnsum[128 + c] * invN - mu * mu;
    float rs = rsqrtf(var + EPS_BN);
    float v = (g_feat[t] - mu) * rs * __ldg(&g[c]) + __ldg(&be[c]);
    g_feat[t] = eluf(v);
}

// ----------------------------- pooling (batch sorted) -----------------------------
__device__ __forceinline__ int lower_bound_batch(int key) {
    int lo = 0, hi = N_NODES;
    while (lo < hi) {
        int mid = (lo + hi) >> 1;
        if (g_batch[mid] < key) lo = mid + 1;
        else hi = mid;
    }
    return lo;
}

__global__ void pool_kernel() {
    int gidx = blockIdx.x;
    __shared__ int se[2];
    if (threadIdx.x == 0) se[0] = lower_bound_batch(gidx);
    if (threadIdx.x == 1) se[1] = lower_bound_batch(gidx + 1);
    __syncthreads();
    int beg = se[0], end = se[1];
    int c = threadIdx.x & 63, sl = threadIdx.x >> 6;
    float sum = 0.f, mx = __int_as_float(0xff800000);
    for (int n = beg + sl; n < end; n += 2) {
        float v = g_feat[n * 64 + c];
        sum += v;
        mx = fmaxf(mx, v);
    }
    __shared__ float shs[128], shm[128];
    shs[threadIdx.x] = sum;
    shm[threadIdx.x] = mx;
    __syncthreads();
    if (sl == 0) {
        sum += shs[64 + c];
        mx = fmaxf(mx, shm[64 + c]);
        int cnt = end - beg;
        float mean = (cnt > 0) ? sum / (float)cnt : 0.f;
        float maxv = (cnt > 0) ? mx : 0.f;
        g_pool[gidx * 128 + c] = mean;
        g_pool[gidx * 128 + 64 + c] = maxv;
    }
}

// ----------------------------- classifier -----------------------------
__global__ void final_kernel(const float* __restrict__ fc1w, const float* __restrict__ fc1b,
                             const float* __restrict__ fc2w, const float* __restrict__ fc2b,
                             float* __restrict__ out) {
    int gidx = blockIdx.x;
    int c = threadIdx.x;  // 64
    __shared__ float hg[128];
    hg[c] = g_pool[gidx * 128 + c];
    hg[c + 64] = g_pool[gidx * 128 + 64 + c];
    __syncthreads();
    float acc = __ldg(&fc1b[c]);
#pragma unroll 8
    for (int k = 0; k < 128; k++) acc += hg[k] * __ldg(&fc1w[k * 64 + c]);
    float z = eluf(acc);
    float part = z * __ldg(&fc2w[c]);
#pragma unroll
    for (int off = 16; off; off >>= 1) part += __shfl_xor_sync(0xffffffffu, part, off);
    __shared__ float warpsum[2];
    if ((c & 31) == 0) warpsum[c >> 5] = part;
    __syncthreads();
    if (c == 0) out[gidx] = warpsum[0] + warpsum[1] + __ldg(&fc2b[0]);
}

// ----------------------------- launch -----------------------------
extern "C" void kernel_launch(void* const* d_in, const int* in_sizes, int n_in,
                              void* d_out, int out_size) {
    const float* x      = (const float*)d_in[0];
    const void*  ei     = d_in[1];
    const void*  batch  = d_in[2];
    const float* W1     = (const float*)d_in[3];
    const float* a1_src = (const float*)d_in[4];
    const float* a1_dst = (const float*)d_in[5];
    const float* b1     = (const float*)d_in[6];
    const float* g1     = (const float*)d_in[7];
    const float* be1    = (const float*)d_in[8];
    const float* W2     = (const float*)d_in[9];
    const float* a2_src = (const float*)d_in[10];
    const float* a2_dst = (const float*)d_in[11];
    const float* b2     = (const float*)d_in[12];
    const float* g2     = (const float*)d_in[13];
    const float* be2    = (const float*)d_in[14];
    const float* W3     = (const float*)d_in[15];
    const float* a3_src = (const float*)d_in[16];
    const float* a3_dst = (const float*)d_in[17];
    const float* b3     = (const float*)d_in[18];
    const float* fc1_w  = (const float*)d_in[19];
    const float* fc1_b  = (const float*)d_in[20];
    const float* fc2_w  = (const float*)d_in[21];
    const float* fc2_b  = (const float*)d_in[22];
    float* out = (float*)d_out;

    const int EB = (E_TOT + 255) / 256;
    const int NB128 = (N_NODES * 128 + 255) / 256;
    const int ATTN_B = (N_NODES + 7) / 8;
    const int GEMM_B = (N_NODES + 63) / 64;

    // graph structure (CSR by dst)
    detect_kernel<<<1, 256>>>(ei);
    zero_deg_kernel<<<(N_NODES + 255) / 256, 256>>>();
    convert_kernel<<<EB, 256>>>(ei, batch);
    scan_partial_kernel<<<SCAN_B, 512>>>();
    scan_mid_kernel<<<1, 128>>>();
    scan_final_kernel<<<SCAN_B, 512>>>();
    fill_kernel<<<EB, 256>>>();

    // ---- layer 1 ----
    gemm1_kernel<<<(N_NODES * 64 + 255) / 256, 256>>>(x, W1);
    als_kernel<<<(N_NODES * 4 + 255) / 256, 256>>>(a1_src, a1_dst);
    attn_kernel<4, 128, false><<<ATTN_B, 256>>>(b1);
    zero_bnsum_kernel<<<1, 256>>>();
    bnstats_kernel<<<(N_NODES + 127) / 128, 128>>>();
    bnnorm_kernel<<<NB128, 256>>>(g1, be1);

    // ---- layer 2 ----
    gemm_kernel<128><<<GEMM_B, 256>>>(W2);
    als_kernel<<<(N_NODES * 4 + 255) / 256, 256>>>(a2_src, a2_dst);
    attn_kernel<4, 128, false><<<ATTN_B, 256>>>(b2);
    zero_bnsum_kernel<<<1, 256>>>();
    bnstats_kernel<<<(N_NODES + 127) / 128, 128>>>();
    bnnorm_kernel<<<NB128, 256>>>(g2, be2);

    // ---- layer 3 ----
    gemm_kernel<64><<<GEMM_B, 256>>>(W3);
    als3_kernel<<<(N_NODES + 255) / 256, 256>>>(a3_src, a3_dst);
    attn_kernel<1, 64, true><<<ATTN_B, 256>>>(b3);

    // ---- readout ----
    pool_kernel<<<N_GRAPHS, 128>>>();
    final_kernel<<<N_GRAPHS, 64>>>(fc1_w, fc1_b, fc2_w, fc2_b, out);
}